// round 14
// baseline (speedup 1.0000x reference)
#include <cuda_runtime.h>
#include <math.h>

namespace {

constexpr int P     = 13;
constexpr int TPB   = 512;
constexpr int D     = 64;
constexpr int NWARP = TPB / 32;

struct c32 { float x, y; };
typedef unsigned long long u64;

__device__ __forceinline__ c32 cmul(c32 a, c32 b) {
    return { fmaf(a.x, b.x, -a.y * b.y), fmaf(a.x, b.y, a.y * b.x) };
}

// ---------------- packed f32x2 helpers (lane0 = sample 2n, lane1 = sample 2n+1) ----------------
__device__ __forceinline__ void upk2(u64 v, float& x, float& y) {
    asm("mov.b64 {%0, %1}, %2;" : "=f"(x), "=f"(y) : "l"(v));
}
__device__ __forceinline__ u64 mul2(u64 a, u64 b) {
    u64 r; asm("mul.rn.f32x2 %0, %1, %2;" : "=l"(r) : "l"(a), "l"(b)); return r;
}
__device__ __forceinline__ u64 fma2(u64 a, u64 b, u64 c) {
    u64 r; asm("fma.rn.f32x2 %0, %1, %2, %3;" : "=l"(r) : "l"(a), "l"(b), "l"(c)); return r;
}
__device__ __forceinline__ u64 add2(u64 a, u64 b) {
    u64 r; asm("add.rn.f32x2 %0, %1, %2;" : "=l"(r) : "l"(a), "l"(b)); return r;
}
__device__ __forceinline__ u64 splat2(float v) {
    u64 r; asm("mov.b64 %0, {%1, %1};" : "=l"(r) : "f"(v)); return r;
}

// packed sample-SoA complex value
struct p2 { u64 r, i; };

// complex multiply, 5 packed ops (NEG1 folds the subtraction)
__device__ __forceinline__ p2 cmulp(p2 a, p2 b, u64 NEG1) {
    p2 o;
    u64 t = mul2(a.i, b.i);
    o.r = fma2(t, NEG1, mul2(a.r, b.r));
    o.i = fma2(a.r, b.i, mul2(a.i, b.r));
    return o;
}

// ---------------- compile-time GF(2) machinery ----------------

__host__ __device__ constexpr int cg_cnot(int i, int x) {
    int cb = P - 1 - i;
    int tb = P - 1 - ((i + 1) % P);
    return ((x >> cb) & 1) ? (x ^ (1 << tb)) : x;
}
__host__ __device__ constexpr int cGmap(int y) {
    for (int i = P - 1; i >= 0; --i) y = cg_cnot(i, y);
    return y;
}
__host__ __device__ constexpr int cGinv(int y) {
    for (int i = 0; i < P; i++) y = cg_cnot(i, y);
    return y;
}
__host__ __device__ constexpr int cpop(int x) { int c = 0; for (int i = 0; i < 16; i++) c += (x >> i) & 1; return c; }
__host__ __device__ constexpr int cctz(int x) { for (int i = 0; i < 16; i++) if ((x >> i) & 1) return i; return -1; }

struct QCData {
    int m2[P];            // layer-2 pair masks  G(e_w)
    int r2[P];            // layer-2 orientation masks (rows of G^-1)
    int rm[P];            // measurement parity masks (rows of G^-2)
    int npos[3][9];       // non-pivot bit positions per batch (ascending)
    int combo[3][16];     // XOR offsets of the 16 coset members
    int lm[3][4];         // local 4-bit pair pattern per gate
    int lml[3][4];        // lowest set bit of lm (canonical selector)
    int lr[3][4];         // local parity pattern per gate
    int rw[3][4];         // full orientation mask per gate (for px)
    int odm[8];           // measurement: per-jj orientation delta (compile-time)
    int mg[4];            // measurement: WHT sig generators
    int kw[P];            // measurement: WHT coefficient index per wire
};

__host__ __device__ constexpr QCData make_qc() {
    QCData q{};
    for (int w = 0; w < P; w++) {
        q.m2[w] = cGmap(1 << (P - 1 - w));
        int r = 0, rm = 0;
        for (int p = 0; p < P; p++) {
            int gi  = cGinv(1 << p);
            int gi2 = cGinv(gi);
            r  |= ((gi  >> (P - 1 - w)) & 1) << p;
            rm |= ((gi2 >> (P - 1 - w)) & 1) << p;
        }
        q.r2[w] = r; q.rm[w] = rm;
    }
    for (int b = 0; b < 3; b++) {
        int f[4] = {}, piv[4] = {};
        for (int i = 0; i < 4; i++) f[i] = q.m2[4 * b + i];
        for (int i = 0; i < 4; i++) {
            for (int j = 0; j < i; j++) if ((f[i] >> piv[j]) & 1) f[i] ^= f[j];
            piv[i] = cctz(f[i]);
            for (int j = 0; j < i; j++) if ((f[j] >> piv[i]) & 1) f[j] ^= f[i];
        }
        int np = 0;
        for (int bit = 0; bit < P; bit++) {
            bool isp = false;
            for (int i = 0; i < 4; i++) if (piv[i] == bit) isp = true;
            if (!isp) q.npos[b][np++] = bit;
        }
        for (int j = 0; j < 16; j++) {
            int c = 0;
            for (int i = 0; i < 4; i++) if ((j >> i) & 1) c ^= f[i];
            q.combo[b][j] = c;
        }
        for (int g = 0; g < 4; g++) {
            int m = q.m2[4 * b + g], r = q.r2[4 * b + g];
            int lm = 0, lr = 0;
            for (int i = 0; i < 4; i++) {
                lm |= ((m >> piv[i]) & 1) << i;
                lr |= (cpop(f[i] & r) & 1) << i;
            }
            q.lm[b][g] = lm;
            q.lml[b][g] = lm & (-lm);
            q.lr[b][g] = lr;
            q.rw[b][g] = r;
        }
    }
    // measurement constants (final gate on wire 12 fused with <Z> readout)
    {
        int m12 = q.m2[12], r12 = q.r2[12];
        for (int jj = 0; jj < 8; jj++) q.odm[jj] = cpop((jj << 10) & r12) & 1;
        for (int i = 0; i < 4; i++) {
            int v = (i < 3) ? (1024 << i) : m12;
            int sgn = 0;
            for (int w = 0; w < P; w++) sgn |= (cpop(v & q.rm[w]) & 1) << w;
            q.mg[i] = sgn;
        }
        for (int w = 0; w < P; w++) {
            int k = 0;
            for (int i = 0; i < 4; i++) k |= ((q.mg[i] >> w) & 1) << i;
            q.kw[w] = k;
        }
    }
    return q;
}

// host-side structural checks only
constexpr QCData QC_HOST = make_qc();
__host__ __device__ constexpr int batch2_support() {
    int s = 0;
    for (int j = 0; j < 16; j++) s |= QC_HOST.combo[2][j];
    return s;
}
static_assert((QC_HOST.m2[12] & 1) == 1, "insert for final gate must be <<1");
static_assert(QC_HOST.npos[2][0] == 4 && QC_HOST.npos[2][8] == 12, "batch2 coset must be low-bit");
static_assert((batch2_support() & ~0x1F) == 0, "batch2 combos must live in bits 0..4");

// SMEM bank-conflict swizzle: XOR bits[7:4] into bits[3:0]. Bijection on [0,8192).
__device__ __forceinline__ int sw(int y) { return y ^ ((y >> 4) & 0xF); }

// ---------------- SMEM layout (float offsets) ----------------
constexpr int SM_SR   = 0;          // re-plane: 8192 u64 (16384 floats)
constexpr int SM_SI   = 16384;      // im-plane: 8192 u64 (16384 floats)
constexpr int SM_COLR = 32768;      // 26 u64 packed colA re (52 floats)
constexpr int SM_COLI = 32820;      // 26 u64 packed colA im (52)
constexpr int SM_MATB = 32872;      // 13*8 floats, shared layer-2 matrices (104)
constexpr int SM_WSUM = 32976;      // NWARP*13 u64 (416 floats)
constexpr int SM_EXPV = 33392;      // 13 u64 (26)
constexpr int SMEM_BYTES = (33392 + 26 + 6) * 4;

// Apply 4 masked gates of batch B to the 16-amp packed-SoA register coset.
// 16 FMA2 per pair (2 samples), zero swaps.
template <int B>
__device__ __forceinline__ void apply_batch_gates(u64* __restrict__ rr, u64* __restrict__ ri,
                                                  const float* __restrict__ matB, int x)
{
    constexpr QCData qc = make_qc();
#pragma unroll
    for (int g = 0; g < 4; g++) {
        const int w = 4 * B + g;
        const float* M = matB + w * 8;
        const c32 u00 = { M[0], M[1] }, u01 = { M[2], M[3] };
        const c32 u10 = { M[4], M[5] }, u11 = { M[6], M[7] };
        const bool px = (__popc(x & qc.rw[B][g]) & 1) != 0;
        const c32 e00 = px ? u11 : u00, e01 = px ? u10 : u01;
        const c32 e10 = px ? u01 : u10, e11 = px ? u00 : u11;
        const u64 R00 = splat2(e00.x), I00 = splat2(e00.y), N00 = splat2(-e00.y);
        const u64 R01 = splat2(e01.x), I01 = splat2(e01.y), N01 = splat2(-e01.y);
        const u64 R10 = splat2(e10.x), I10 = splat2(e10.y), N10 = splat2(-e10.y);
        const u64 R11 = splat2(e11.x), I11 = splat2(e11.y), N11 = splat2(-e11.y);
#pragma unroll
        for (int j = 0; j < 16; j++) {
            if (j & qc.lml[B][g]) continue;                   // canonical of each pair
            const int jp  = j ^ qc.lm[B][g];                  // compile-time partner
            const bool oc = (cpop(j & qc.lr[B][g]) & 1) != 0; // compile-time
            // row0 = oc ? (e11,e10) : (e00,e01); row1 = oc ? (e01,e00) : (e10,e11)
            const u64 Ar = oc ? R11 : R00, Ai = oc ? I11 : I00, An = oc ? N11 : N00;
            const u64 Br = oc ? R10 : R01, Bi = oc ? I10 : I01, Bn = oc ? N10 : N01;
            const u64 Cr = oc ? R01 : R10, Ci = oc ? I01 : I10, Cn = oc ? N01 : N10;
            const u64 Dr = oc ? R00 : R11, Di = oc ? I00 : I11, Dn = oc ? N00 : N11;
            const u64 ar = rr[j], ai = ri[j], br = rr[jp], bi = ri[jp];
            rr[j]  = fma2(ar, Ar, fma2(ai, An, fma2(br, Br, mul2(bi, Bn))));
            ri[j]  = fma2(ar, Ai, fma2(ai, Ar, fma2(br, Bi, mul2(bi, Br))));
            rr[jp] = fma2(ar, Cr, fma2(ai, Cn, fma2(br, Dr, mul2(bi, Dn))));
            ri[jp] = fma2(ar, Ci, fma2(ai, Cr, fma2(br, Di, mul2(bi, Dr))));
        }
    }
}

template <int B>
__device__ __forceinline__ void do_batch(u64* __restrict__ sr, u64* __restrict__ si,
                                         const float* __restrict__ matB, int tid)
{
    constexpr QCData qc = make_qc();
    int x = 0;
#pragma unroll
    for (int i = 0; i < 9; i++) x |= ((tid >> i) & 1) << qc.npos[B][i];

    u64 rr[16], ri[16];
#pragma unroll
    for (int j = 0; j < 16; j++) {
        const int a = sw(x ^ qc.combo[B][j]);
        rr[j] = sr[a]; ri[j] = si[a];
    }
    apply_batch_gates<B>(rr, ri, matB, x);
#pragma unroll
    for (int j = 0; j < 16; j++) {
        const int a = sw(x ^ qc.combo[B][j]);
        sr[a] = rr[j]; si[a] = ri[j];
    }
}

__global__ void __launch_bounds__(TPB, 1)
qlc_kernel(const float* __restrict__ h,
           const float* __restrict__ enc_w,
           const float* __restrict__ enc_b,
           const float* __restrict__ qw,
           const float* __restrict__ dec_w,
           const float* __restrict__ alpha,
           float* __restrict__ out)
{
    extern __shared__ float smemf[];
    u64*   sr   = (u64*)(smemf + SM_SR);
    u64*   si   = (u64*)(smemf + SM_SI);
    u64*   colR = (u64*)(smemf + SM_COLR);
    u64*   colI = (u64*)(smemf + SM_COLI);
    float* matB = smemf + SM_MATB;
    u64*   wsum = (u64*)(smemf + SM_WSUM);
    u64*   expv = (u64*)(smemf + SM_EXPV);

    const int n = blockIdx.x;                 // sample pair (2n, 2n+1)
    const int tid = threadIdx.x, wid = tid >> 5, lane = tid & 31;

    // ================= Phase A =================
    // warps 0..12: wire w — angles for both samples, lanes 0/1 build packed colA.
    // warp 13 lanes 0..12: shared layer-2 gate matrices.
    if (wid < P) {
        float angv[6];
#pragma unroll
        for (int sb = 0; sb < 2; sb++) {
            const float* hrow = h + ((2 * n + sb) * P + wid) * D;
            const float h0 = hrow[lane], h1 = hrow[lane + 32];
#pragma unroll
            for (int a = 0; a < 3; a++) {
                float v = h0 * enc_w[a * D + lane] + h1 * enc_w[a * D + lane + 32];
#pragma unroll
                for (int off = 16; off; off >>= 1)
                    v += __shfl_xor_sync(0xffffffffu, v, off);
                angv[sb * 3 + a] = v + enc_b[a];
            }
        }
        if (lane < 2) {
            const int w = wid;
            float a0 = angv[lane * 3 + 0], a1 = angv[lane * 3 + 1], a2 = angv[lane * 3 + 2];
            float q0 = qw[w * 3 + 0], q1 = qw[w * 3 + 1], q2 = qw[w * 3 + 2];  // layer 0
            float sA, cA; sincosf(0.5f * a0, &sA, &cA);
            c32 v0 = { cA, 0.f }, v1 = { 0.f, -sA };                 // RX col0
            float sB, cB; sincosf(0.5f * a1, &sB, &cB);              // RY
            c32 t0 = { cB * v0.x - sB * v1.x, cB * v0.y - sB * v1.y };
            c32 t1 = { sB * v0.x + cB * v1.x, sB * v0.y + cB * v1.y };
            float sC, cC; sincosf(0.5f * a2, &sC, &cC);              // RZ
            v0 = cmul({ cC, -sC }, t0); v1 = cmul({ cC, sC }, t1);
            float s0, c0; sincosf(0.5f * q0, &s0, &c0);              // RY
            t0 = { c0 * v0.x - s0 * v1.x, c0 * v0.y - s0 * v1.y };
            t1 = { s0 * v0.x + c0 * v1.x, s0 * v0.y + c0 * v1.y };
            float s1, c1; sincosf(0.5f * q1, &s1, &c1);              // RZ
            v0 = cmul({ c1, -s1 }, t0); v1 = cmul({ c1, s1 }, t1);
            float s2, c2; sincosf(0.5f * q2, &s2, &c2);              // RY
            t0 = { c2 * v0.x - s2 * v1.x, c2 * v0.y - s2 * v1.y };
            t1 = { s2 * v0.x + c2 * v1.x, s2 * v0.y + c2 * v1.y };
            // packed slots: u64 slot k occupies floats [2k, 2k+1]; lane sb writes half sb
            float* cRf = smemf + SM_COLR;
            float* cIf = smemf + SM_COLI;
            cRf[(w * 2 + 0) * 2 + lane] = t0.x;  cIf[(w * 2 + 0) * 2 + lane] = t0.y;
            cRf[(w * 2 + 1) * 2 + lane] = t1.x;  cIf[(w * 2 + 1) * 2 + lane] = t1.y;
        }
    } else if (wid == 13 && lane < P) {
        const int w = lane;
        float q0 = qw[(P + w) * 3 + 0], q1 = qw[(P + w) * 3 + 1], q2 = qw[(P + w) * 3 + 2]; // layer 1
        float s0, c0; sincosf(0.5f * q0, &s0, &c0);
        float s1, c1; sincosf(0.5f * q1, &s1, &c1);
        float s2, c2; sincosf(0.5f * q2, &s2, &c2);
        c32 e0 = { c1, -s1 }, e1 = { c1, s1 };
        c32 m00 = {  e0.x * c0,  e0.y * c0 }, m01 = { -e0.x * s0, -e0.y * s0 };
        c32 m10 = {  e1.x * s0,  e1.y * s0 }, m11 = {  e1.x * c0,  e1.y * c0 };
        c32 u00 = { c2 * m00.x - s2 * m10.x, c2 * m00.y - s2 * m10.y };
        c32 u01 = { c2 * m01.x - s2 * m11.x, c2 * m01.y - s2 * m11.y };
        c32 u10 = { s2 * m00.x + c2 * m10.x, s2 * m00.y + c2 * m10.y };
        c32 u11 = { s2 * m01.x + c2 * m11.x, s2 * m01.y + c2 * m11.y };
        float* M = matB + w * 8;
        M[0] = u00.x; M[1] = u00.y; M[2] = u01.x; M[3] = u01.y;
        M[4] = u10.x; M[5] = u10.y; M[6] = u11.x; M[7] = u11.y;
    }
    __syncthreads();

    const u64 NEG1 = splat2(-1.0f);

    // ---- product-state construction FUSED with batch-2 gates (packed SoA) ----
    {
        constexpr QCData qc = make_qc();
        auto colp = [&](int w, int b) -> p2 { return { colR[w * 2 + b], colI[w * 2 + b] }; };
        p2 pre = colp(0, (tid >> 8) & 1);
#pragma unroll
        for (int w = 1; w < 8; w++) pre = cmulp(pre, colp(w, (tid >> (8 - w)) & 1), NEG1);
        p2 ph[4];
#pragma unroll
        for (int t = 0; t < 4; t++)
            ph[t] = cmulp(pre, cmulp(colp(8, t >> 1), colp(9, t & 1), NEG1), NEG1);
        const int t0b = tid & 1;
        p2 phe[4];
#pragma unroll
        for (int t = 0; t < 4; t++) phe[t] = t0b ? ph[t ^ 2] : ph[t];
        p2 t2[4];
#pragma unroll
        for (int t = 0; t < 4; t++) t2[t] = cmulp(colp(10, t >> 1), colp(11, t & 1), NEG1);
        p2 pl[8];
#pragma unroll
        for (int u = 0; u < 8; u++) pl[u] = cmulp(t2[u >> 1], colp(12, u & 1), NEG1);

        u64 rr[16], ri[16];
#pragma unroll
        for (int j = 0; j < 16; j++) {
            const int cj = qc.combo[2][j];
            p2 v = cmulp(phe[(cj >> 3) & 3], pl[cj & 7], NEG1);
            rr[j] = v.r; ri[j] = v.i;
        }
        const int x = tid << 4;
        apply_batch_gates<2>(rr, ri, matB, x);
#pragma unroll
        for (int j = 0; j < 16; j++) {
            const int a = sw(x ^ qc.combo[2][j]);
            sr[a] = rr[j]; si[a] = ri[j];
        }
    }
    __syncthreads();

    do_batch<0>(sr, si, matB, tid); __syncthreads();
    do_batch<1>(sr, si, matB, tid); __syncthreads();

    // ---- final gate (wire 12) fused with <Z_w> via compile-time WHT signs ----
    {
        constexpr QCData qc = make_qc();
        constexpr int m12 = qc.m2[12];
        constexpr int r12 = qc.r2[12];
        const float* M = matB + 12 * 8;
        const c32 u00 = { M[0], M[1] }, u01 = { M[2], M[3] };
        const c32 u10 = { M[4], M[5] }, u11 = { M[6], M[7] };
        const int  x0 = tid << 1;
        const bool o0 = (__popc(x0 & r12) & 1) != 0;
        const c32 e00 = o0 ? u11 : u00, e01 = o0 ? u10 : u01;
        const c32 e10 = o0 ? u01 : u10, e11 = o0 ? u00 : u11;
        const u64 R00 = splat2(e00.x), I00 = splat2(e00.y), N00 = splat2(-e00.y);
        const u64 R01 = splat2(e01.x), I01 = splat2(e01.y), N01 = splat2(-e01.y);
        const u64 R10 = splat2(e10.x), I10 = splat2(e10.y), N10 = splat2(-e10.y);
        const u64 R11 = splat2(e11.x), I11 = splat2(e11.y), N11 = splat2(-e11.y);

        u64 p[16];
#pragma unroll
        for (int jj = 0; jj < 8; jj++) {
            const int x  = x0 ^ (jj << 10);
            const int xp = x ^ m12;
            const int sa = sw(x), sb = sw(xp);
            const u64 ar = sr[sa], ai = si[sa], br = sr[sb], bi = si[sb];
            const bool od = qc.odm[jj] != 0;              // compile-time
            const u64 Ar = od ? R11 : R00, Ai = od ? I11 : I00, An = od ? N11 : N00;
            const u64 Br = od ? R10 : R01, Bi = od ? I10 : I01, Bn = od ? N10 : N01;
            const u64 Cr = od ? R01 : R10, Ci = od ? I01 : I10, Cn = od ? N01 : N10;
            const u64 Dr = od ? R00 : R11, Di = od ? I00 : I11, Dn = od ? N00 : N11;
            const u64 n0r = fma2(ar, Ar, fma2(ai, An, fma2(br, Br, mul2(bi, Bn))));
            const u64 n0i = fma2(ar, Ai, fma2(ai, Ar, fma2(br, Bi, mul2(bi, Br))));
            const u64 n1r = fma2(ar, Cr, fma2(ai, Cn, fma2(br, Dr, mul2(bi, Dn))));
            const u64 n1i = fma2(ar, Ci, fma2(ai, Cr, fma2(br, Di, mul2(bi, Dr))));
            p[jj]     = fma2(n0r, n0r, mul2(n0i, n0i));   // packed prob at x
            p[jj | 8] = fma2(n1r, n1r, mul2(n1i, n1i));   // packed prob at x^m
        }
        // 16-point Walsh–Hadamard, packed over both samples (signs compile-time)
#pragma unroll
        for (int st = 1; st < 16; st <<= 1) {
#pragma unroll
            for (int k = 0; k < 16; k++)
                if (!(k & st)) {
                    const u64 a = p[k], b = p[k ^ st];
                    p[k] = add2(a, b);
                    p[k ^ st] = fma2(b, NEG1, a);
                }
        }
        int sig0 = 0;
#pragma unroll
        for (int w = 0; w < P; w++) sig0 |= (__popc(x0 & qc.rm[w]) & 1) << w;
#pragma unroll
        for (int w = 0; w < P; w++) {
            u64 v = p[qc.kw[w]];
            if ((sig0 >> w) & 1) v = mul2(v, NEG1);
#pragma unroll
            for (int off = 16; off; off >>= 1)
                v = add2(v, __shfl_xor_sync(0xffffffffu, v, off));
            if (lane == 0) wsum[wid * P + w] = v;
        }
    }
    __syncthreads();
    if (tid < P) {
        u64 v = wsum[tid];
        for (int k = 1; k < NWARP; k++) v = add2(v, wsum[k * P + tid]);
        expv[tid] = v;
    }
    __syncthreads();

    // ---- decode + residual for both samples ----
    const float al = alpha[0];
    const int base0 = (2 * n) * P * D;
    const int PD = P * D;
    for (int e = tid; e < PD; e += TPB) {
        const int w = e >> 6;
        const int d = e & 63;
        float ex, ey; upk2(expv[w], ex, ey);
        const float dv = al * dec_w[d];
        out[base0 + e]      = h[base0 + e]      + ex * dv;
        out[base0 + PD + e] = h[base0 + PD + e] + ey * dv;
    }
}

} // anonymous namespace

extern "C" void kernel_launch(void* const* d_in, const int* in_sizes, int n_in,
                              void* d_out, int out_size)
{
    const float* h     = (const float*)d_in[0];
    const float* enc_w = (const float*)d_in[1];
    const float* enc_b = (const float*)d_in[2];
    const float* qw    = (const float*)d_in[3];
    const float* dec_w = (const float*)d_in[4];
    const float* alpha = (const float*)d_in[5];
    float* out = (float*)d_out;

    const int nsamp = in_sizes[0] / (P * D);   // B*T (even)
    const int npair = nsamp / 2;

    cudaFuncSetAttribute(qlc_kernel, cudaFuncAttributeMaxDynamicSharedMemorySize, SMEM_BYTES);
    qlc_kernel<<<npair, TPB, SMEM_BYTES>>>(h, enc_w, enc_b, qw, dec_w, alpha, out);
}

// round 15
// speedup vs baseline: 1.4267x; 1.4267x over previous
#include <cuda_runtime.h>
#include <math.h>

namespace {

constexpr int P     = 13;
constexpr int TPB   = 512;
constexpr int D     = 64;
constexpr int NWARP = TPB / 32;

struct c32 { float x, y; };
typedef unsigned long long u64;

__device__ __forceinline__ c32 cmul(c32 a, c32 b) {
    return { fmaf(a.x, b.x, -a.y * b.y), fmaf(a.x, b.y, a.y * b.x) };
}
__device__ __forceinline__ c32 cadd(c32 a, c32 b) { return { a.x + b.x, a.y + b.y }; }

// ---------------- packed f32x2 helpers ----------------
__device__ __forceinline__ u64 pk2(float x, float y) {
    u64 r; asm("mov.b64 %0, {%1, %2};" : "=l"(r) : "f"(x), "f"(y)); return r;
}
__device__ __forceinline__ void upk2(u64 v, float& x, float& y) {
    asm("mov.b64 {%0, %1}, %2;" : "=f"(x), "=f"(y) : "l"(v));
}
__device__ __forceinline__ u64 swp2(u64 v) {
    u64 r;
    asm("{ .reg .b32 lo, hi; mov.b64 {lo, hi}, %1; mov.b64 %0, {hi, lo}; }"
        : "=l"(r) : "l"(v));
    return r;
}
__device__ __forceinline__ u64 mul2(u64 a, u64 b) {
    u64 r; asm("mul.rn.f32x2 %0, %1, %2;" : "=l"(r) : "l"(a), "l"(b)); return r;
}
__device__ __forceinline__ u64 fma2(u64 a, u64 b, u64 c) {
    u64 r; asm("fma.rn.f32x2 %0, %1, %2, %3;" : "=l"(r) : "l"(a), "l"(b), "l"(c)); return r;
}
__device__ __forceinline__ u64 splat_xx(c32 m) {
    u64 r; asm("mov.b64 %0, {%1, %1};" : "=l"(r) : "f"(m.x)); return r;
}
__device__ __forceinline__ u64 splat_yn(c32 m) {
    u64 r; asm("mov.b64 %0, {%1, %2};" : "=l"(r) : "f"(-m.y), "f"(m.y)); return r;
}
// n = m0*va + m1*vb  (complex, packed):  va,vb packed {x,y}; vas,vbs their swaps {y,x}
__device__ __forceinline__ u64 bfly(u64 va, u64 vas, u64 vb, u64 vbs,
                                    u64 m0xx, u64 m0yn, u64 m1xx, u64 m1yn) {
    return fma2(va, m0xx, fma2(vas, m0yn, fma2(vb, m1xx, mul2(vbs, m1yn))));
}

// ---------------- compile-time GF(2) machinery ----------------

__host__ __device__ constexpr int cg_cnot(int i, int x) {
    int cb = P - 1 - i;
    int tb = P - 1 - ((i + 1) % P);
    return ((x >> cb) & 1) ? (x ^ (1 << tb)) : x;
}
__host__ __device__ constexpr int cGmap(int y) {
    for (int i = P - 1; i >= 0; --i) y = cg_cnot(i, y);
    return y;
}
__host__ __device__ constexpr int cGinv(int y) {
    for (int i = 0; i < P; i++) y = cg_cnot(i, y);
    return y;
}
__host__ __device__ constexpr int cpop(int x) { int c = 0; for (int i = 0; i < 16; i++) c += (x >> i) & 1; return c; }
__host__ __device__ constexpr int cctz(int x) { for (int i = 0; i < 16; i++) if ((x >> i) & 1) return i; return -1; }

struct QCData {
    int m2[P];            // layer-2 pair masks  G(e_w)
    int r2[P];            // layer-2 orientation masks (rows of G^-1)
    int rm[P];            // measurement parity masks (rows of G^-2)
    int npos[3][9];       // non-pivot bit positions per batch (ascending)
    int combo[3][16];     // XOR offsets of the 16 coset members
    int lm[3][4];         // local 4-bit pair pattern per gate
    int lml[3][4];        // lowest set bit of lm (canonical selector)
    int lr[3][4];         // local parity pattern per gate
    int rw[3][4];         // full orientation mask per gate (for px)
    int odm[8];           // measurement: per-jj orientation delta (compile-time)
    int mg[4];            // measurement: WHT sig generators
    int kw[P];            // measurement: WHT coefficient index per wire
};

__host__ __device__ constexpr QCData make_qc() {
    QCData q{};
    for (int w = 0; w < P; w++) {
        q.m2[w] = cGmap(1 << (P - 1 - w));
        int r = 0, rm = 0;
        for (int p = 0; p < P; p++) {
            int gi  = cGinv(1 << p);
            int gi2 = cGinv(gi);
            r  |= ((gi  >> (P - 1 - w)) & 1) << p;
            rm |= ((gi2 >> (P - 1 - w)) & 1) << p;
        }
        q.r2[w] = r; q.rm[w] = rm;
    }
    for (int b = 0; b < 3; b++) {
        int f[4] = {}, piv[4] = {};
        for (int i = 0; i < 4; i++) f[i] = q.m2[4 * b + i];
        for (int i = 0; i < 4; i++) {
            for (int j = 0; j < i; j++) if ((f[i] >> piv[j]) & 1) f[i] ^= f[j];
            piv[i] = cctz(f[i]);
            for (int j = 0; j < i; j++) if ((f[j] >> piv[i]) & 1) f[j] ^= f[i];
        }
        int np = 0;
        for (int bit = 0; bit < P; bit++) {
            bool isp = false;
            for (int i = 0; i < 4; i++) if (piv[i] == bit) isp = true;
            if (!isp) q.npos[b][np++] = bit;
        }
        for (int j = 0; j < 16; j++) {
            int c = 0;
            for (int i = 0; i < 4; i++) if ((j >> i) & 1) c ^= f[i];
            q.combo[b][j] = c;
        }
        for (int g = 0; g < 4; g++) {
            int m = q.m2[4 * b + g], r = q.r2[4 * b + g];
            int lm = 0, lr = 0;
            for (int i = 0; i < 4; i++) {
                lm |= ((m >> piv[i]) & 1) << i;
                lr |= (cpop(f[i] & r) & 1) << i;
            }
            q.lm[b][g] = lm;
            q.lml[b][g] = lm & (-lm);
            q.lr[b][g] = lr;
            q.rw[b][g] = r;
        }
    }
    // measurement constants (final gate on wire 12 fused with <Z> readout)
    {
        int m12 = q.m2[12], r12 = q.r2[12];
        for (int jj = 0; jj < 8; jj++) q.odm[jj] = cpop((jj << 10) & r12) & 1;
        for (int i = 0; i < 4; i++) {
            int v = (i < 3) ? (1024 << i) : m12;    // idx-bit deltas in amp-index space
            int sgn = 0;
            for (int w = 0; w < P; w++) sgn |= (cpop(v & q.rm[w]) & 1) << w;
            q.mg[i] = sgn;
        }
        for (int w = 0; w < P; w++) {
            int k = 0;
            for (int i = 0; i < 4; i++) k |= ((q.mg[i] >> w) & 1) << i;
            q.kw[w] = k;
        }
    }
    return q;
}

// host-side structural checks only (device code re-materializes its own local constexpr copy)
constexpr QCData QC_HOST = make_qc();
__host__ __device__ constexpr int batch2_support() {
    int s = 0;
    for (int j = 0; j < 16; j++) s |= QC_HOST.combo[2][j];
    return s;
}
static_assert((QC_HOST.m2[12] & 1) == 1, "insert for final gate must be <<1");
static_assert(QC_HOST.npos[2][0] == 4 && QC_HOST.npos[2][8] == 12, "batch2 coset must be low-bit");
static_assert((batch2_support() & ~0x1F) == 0, "batch2 combos must live in bits 0..4");

// SMEM bank-conflict swizzle: XOR bits[7:4] into bits[3:0]. Bijection on [0,8192).
__device__ __forceinline__ int sw(int y) { return y ^ ((y >> 4) & 0xF); }

// ---------------- SMEM layout (floats) ----------------
constexpr int SM_S    = 0;                    // 8192 c32 = 16384 floats
constexpr int SM_COLA = 16384;                // 13*2 c32 = 52 floats (8B aligned)
constexpr int SM_MATB = 16436;                // 13*8 = 104 floats (8B aligned)
constexpr int SM_WSUM = 16540;                // NWARP*13 = 208
constexpr int SM_EXPV = 16748;                // 13
constexpr int SMEM_BYTES = (16748 + 13 + 3) * 4;

// Apply 4 masked gates of batch B to the 16-amp packed register coset.
template <int B>
__device__ __forceinline__ void apply_batch_gates(u64* __restrict__ reg,
                                                  const float* __restrict__ matB, int x)
{
    constexpr QCData qc = make_qc();
#pragma unroll
    for (int g = 0; g < 4; g++) {
        const int w = 4 * B + g;
        const float* M = matB + w * 8;
        const c32 u00 = { M[0], M[1] }, u01 = { M[2], M[3] };
        const c32 u10 = { M[4], M[5] }, u11 = { M[6], M[7] };
        const bool px = (__popc(x & qc.rw[B][g]) & 1) != 0;
        const c32 e00 = px ? u11 : u00, e01 = px ? u10 : u01;
        const c32 e10 = px ? u01 : u10, e11 = px ? u00 : u11;
        const u64 E0xx = splat_xx(e00), E0yn = splat_yn(e00);
        const u64 E1xx = splat_xx(e01), E1yn = splat_yn(e01);
        const u64 E2xx = splat_xx(e10), E2yn = splat_yn(e10);
        const u64 E3xx = splat_xx(e11), E3yn = splat_yn(e11);
#pragma unroll
        for (int j = 0; j < 16; j++) {
            if (j & qc.lml[B][g]) continue;                  // canonical of each pair
            const int jp  = j ^ qc.lm[B][g];                 // compile-time partner
            const bool oc = (cpop(j & qc.lr[B][g]) & 1) != 0; // compile-time
            const u64 m00xx = oc ? E3xx : E0xx, m00yn = oc ? E3yn : E0yn;
            const u64 m01xx = oc ? E2xx : E1xx, m01yn = oc ? E2yn : E1yn;
            const u64 m10xx = oc ? E1xx : E2xx, m10yn = oc ? E1yn : E2yn;
            const u64 m11xx = oc ? E0xx : E3xx, m11yn = oc ? E0yn : E3yn;
            const u64 va = reg[j], vb = reg[jp];
            const u64 vas = swp2(va), vbs = swp2(vb);
            reg[j]  = bfly(va, vas, vb, vbs, m00xx, m00yn, m01xx, m01yn);
            reg[jp] = bfly(va, vas, vb, vbs, m10xx, m10yn, m11xx, m11yn);
        }
    }
}

template <int B>
__device__ __forceinline__ void do_batch(u64* __restrict__ s64,
                                         const float* __restrict__ matB, int tid)
{
    constexpr QCData qc = make_qc();
    int x = 0;
#pragma unroll
    for (int i = 0; i < 9; i++) x |= ((tid >> i) & 1) << qc.npos[B][i];

    u64 reg[16];
#pragma unroll
    for (int j = 0; j < 16; j++) reg[j] = s64[sw(x ^ qc.combo[B][j])];

    apply_batch_gates<B>(reg, matB, x);

#pragma unroll
    for (int j = 0; j < 16; j++) s64[sw(x ^ qc.combo[B][j])] = reg[j];
}

__global__ void __launch_bounds__(TPB, 2)
qlc_kernel(const float* __restrict__ h,
           const float* __restrict__ enc_w,
           const float* __restrict__ enc_b,
           const float* __restrict__ qw,
           const float* __restrict__ dec_w,
           const float* __restrict__ alpha,
           float* __restrict__ out)
{
    extern __shared__ float smemf[];
    u64*   s64  = (u64*)(smemf + SM_S);
    c32*   colA = (c32*)(smemf + SM_COLA);   // [13][2] fused (enc+L1) column-0
    float* matB = smemf + SM_MATB;           // [13][8] layer-2 gate matrices
    float* wsum = smemf + SM_WSUM;
    float* expv = smemf + SM_EXPV;

    const int n = blockIdx.x, tid = threadIdx.x, wid = tid >> 5, lane = tid & 31;

    // ================= Phase A (fully parallel constants) =================
    // warps 0..12: wire w = wid — warp-reduced angles, lane 0 builds colA[w].
    // warp 13 lanes 0..12: shared layer-2 gate matrices (concurrent, no serialization).
    if (wid < P) {
        const float* hrow = h + (n * P + wid) * D;
        const float h0 = hrow[lane], h1 = hrow[lane + 32];
        float aa[3];
#pragma unroll
        for (int a = 0; a < 3; a++) {
            float v = h0 * enc_w[a * D + lane] + h1 * enc_w[a * D + lane + 32];
#pragma unroll
            for (int off = 16; off; off >>= 1)
                v += __shfl_xor_sync(0xffffffffu, v, off);
            aa[a] = v;
        }
        if (lane == 0) {
            const int w = wid;
            float a0 = aa[0] + enc_b[0], a1 = aa[1] + enc_b[1], a2 = aa[2] + enc_b[2];
            float q0 = qw[w * 3 + 0], q1 = qw[w * 3 + 1], q2 = qw[w * 3 + 2];  // layer 0
            float sA, cA; sincosf(0.5f * a0, &sA, &cA);
            c32 v0 = { cA, 0.f }, v1 = { 0.f, -sA };                 // RX col0
            float sB, cB; sincosf(0.5f * a1, &sB, &cB);              // RY
            c32 t0 = { cB * v0.x - sB * v1.x, cB * v0.y - sB * v1.y };
            c32 t1 = { sB * v0.x + cB * v1.x, sB * v0.y + cB * v1.y };
            float sC, cC; sincosf(0.5f * a2, &sC, &cC);              // RZ
            v0 = cmul({ cC, -sC }, t0); v1 = cmul({ cC, sC }, t1);
            float s0, c0; sincosf(0.5f * q0, &s0, &c0);              // RY
            t0 = { c0 * v0.x - s0 * v1.x, c0 * v0.y - s0 * v1.y };
            t1 = { s0 * v0.x + c0 * v1.x, s0 * v0.y + c0 * v1.y };
            float s1, c1; sincosf(0.5f * q1, &s1, &c1);              // RZ
            v0 = cmul({ c1, -s1 }, t0); v1 = cmul({ c1, s1 }, t1);
            float s2, c2; sincosf(0.5f * q2, &s2, &c2);              // RY
            t0 = { c2 * v0.x - s2 * v1.x, c2 * v0.y - s2 * v1.y };
            t1 = { s2 * v0.x + c2 * v1.x, s2 * v0.y + c2 * v1.y };
            colA[w * 2 + 0] = t0; colA[w * 2 + 1] = t1;
        }
    } else if (wid == 13 && lane < P) {
        const int w = lane;
        float q0 = qw[(P + w) * 3 + 0], q1 = qw[(P + w) * 3 + 1], q2 = qw[(P + w) * 3 + 2]; // layer 1
        float s0, c0; sincosf(0.5f * q0, &s0, &c0);
        float s1, c1; sincosf(0.5f * q1, &s1, &c1);
        float s2, c2; sincosf(0.5f * q2, &s2, &c2);
        // M1 = RZ(q1)*RY(q0)
        c32 e0 = { c1, -s1 }, e1 = { c1, s1 };
        c32 m00 = {  e0.x * c0,  e0.y * c0 }, m01 = { -e0.x * s0, -e0.y * s0 };
        c32 m10 = {  e1.x * s0,  e1.y * s0 }, m11 = {  e1.x * c0,  e1.y * c0 };
        // U = RY(q2)*M1
        c32 u00 = { c2 * m00.x - s2 * m10.x, c2 * m00.y - s2 * m10.y };
        c32 u01 = { c2 * m01.x - s2 * m11.x, c2 * m01.y - s2 * m11.y };
        c32 u10 = { s2 * m00.x + c2 * m10.x, s2 * m00.y + c2 * m10.y };
        c32 u11 = { s2 * m01.x + c2 * m11.x, s2 * m01.y + c2 * m11.y };
        float* M = matB + w * 8;
        M[0] = u00.x; M[1] = u00.y; M[2] = u01.x; M[3] = u01.y;
        M[4] = u10.x; M[5] = u10.y; M[6] = u11.x; M[7] = u11.y;
    }
    __syncthreads();

    // ---- product-state construction FUSED with batch-2 gates (registers only) ----
    {
        constexpr QCData qc = make_qc();
        // x = tid<<4 (batch-2 coset representative; static_asserted structure).
        // Common prefix over wires 0..7 (bits 12..5):
        c32 pre = colA[0 * 2 + ((tid >> 8) & 1)];
#pragma unroll
        for (int w = 1; w < 8; w++) pre = cmul(pre, colA[w * 2 + ((tid >> (8 - w)) & 1)]);
        // wires 8,9 (bits 4,3), with pre folded in:
        c32 ph[4];
#pragma unroll
        for (int t = 0; t < 4; t++)
            ph[t] = cmul(pre, cmul(colA[8 * 2 + (t >> 1)], colA[9 * 2 + (t & 1)]));
        const int t0b = tid & 1;                  // runtime bit 4 of x
        c32 phe[4];
#pragma unroll
        for (int t = 0; t < 4; t++) phe[t] = t0b ? ph[t ^ 2] : ph[t];
        // wires 10,11,12 (bits 2,1,0):
        c32 t2[4];
#pragma unroll
        for (int t = 0; t < 4; t++) t2[t] = cmul(colA[10 * 2 + (t >> 1)], colA[11 * 2 + (t & 1)]);
        c32 pl[8];
#pragma unroll
        for (int u = 0; u < 8; u++) pl[u] = cmul(t2[u >> 1], colA[12 * 2 + (u & 1)]);

        u64 reg[16];
#pragma unroll
        for (int j = 0; j < 16; j++) {
            const int cj = qc.combo[2][j];
            const c32 v = cmul(phe[(cj >> 3) & 3], pl[cj & 7]);
            reg[j] = pk2(v.x, v.y);
        }
        const int x = tid << 4;
        apply_batch_gates<2>(reg, matB, x);
#pragma unroll
        for (int j = 0; j < 16; j++) s64[sw(x ^ qc.combo[2][j])] = reg[j];
    }
    __syncthreads();

    // ---- remaining layer-2 gate batches ----
    do_batch<0>(s64, matB, tid); __syncthreads();
    do_batch<1>(s64, matB, tid); __syncthreads();

    // ---- final gate (wire 12) fused with <Z_w> via compile-time WHT signs ----
    {
        constexpr QCData qc = make_qc();
        constexpr int m12 = qc.m2[12];
        constexpr int r12 = qc.r2[12];
        const float* M = matB + 12 * 8;
        const c32 u00 = { M[0], M[1] }, u01 = { M[2], M[3] };
        const c32 u10 = { M[4], M[5] }, u11 = { M[6], M[7] };
        const int  x0 = tid << 1;                 // insert(tid), lomask==0
        const bool o0 = (__popc(x0 & r12) & 1) != 0;
        const c32 e00 = o0 ? u11 : u00, e01 = o0 ? u10 : u01;
        const c32 e10 = o0 ? u01 : u10, e11 = o0 ? u00 : u11;
        const u64 E0xx = splat_xx(e00), E0yn = splat_yn(e00);
        const u64 E1xx = splat_xx(e01), E1yn = splat_yn(e01);
        const u64 E2xx = splat_xx(e10), E2yn = splat_yn(e10);
        const u64 E3xx = splat_xx(e11), E3yn = splat_yn(e11);

        float p[16];
#pragma unroll
        for (int jj = 0; jj < 8; jj++) {
            const int x  = x0 ^ (jj << 10);
            const int xp = x ^ m12;
            const u64 va = s64[sw(x)], vb = s64[sw(xp)];
            const u64 vas = swp2(va), vbs = swp2(vb);
            const bool od = qc.odm[jj] != 0;       // compile-time
            const u64 m00xx = od ? E3xx : E0xx, m00yn = od ? E3yn : E0yn;
            const u64 m01xx = od ? E2xx : E1xx, m01yn = od ? E2yn : E1yn;
            const u64 m10xx = od ? E1xx : E2xx, m10yn = od ? E1yn : E2yn;
            const u64 m11xx = od ? E0xx : E3xx, m11yn = od ? E0yn : E3yn;
            const u64 n0 = bfly(va, vas, vb, vbs, m00xx, m00yn, m01xx, m01yn);
            const u64 n1 = bfly(va, vas, vb, vbs, m10xx, m10yn, m11xx, m11yn);
            float n0x, n0y, n1x, n1y;
            upk2(n0, n0x, n0y); upk2(n1, n1x, n1y);
            p[jj]     = fmaf(n0x, n0x, n0y * n0y);   // prob at index x
            p[jj | 8] = fmaf(n1x, n1x, n1y * n1y);   // prob at index x^m
        }
        // 16-point Walsh–Hadamard (all signs compile-time)
#pragma unroll
        for (int st = 1; st < 16; st <<= 1) {
#pragma unroll
            for (int k = 0; k < 16; k++)
                if (!(k & st)) {
                    const float a = p[k], b = p[k ^ st];
                    p[k] = a + b; p[k ^ st] = a - b;
                }
        }
        int sig0 = 0;
#pragma unroll
        for (int w = 0; w < P; w++) sig0 |= (__popc(x0 & qc.rm[w]) & 1) << w;
#pragma unroll
        for (int w = 0; w < P; w++) {
            float v = p[qc.kw[w]];
            v = ((sig0 >> w) & 1) ? -v : v;
#pragma unroll
            for (int off = 16; off; off >>= 1)
                v += __shfl_xor_sync(0xffffffffu, v, off);
            if (lane == 0) wsum[wid * P + w] = v;
        }
    }
    __syncthreads();
    if (tid < P) {
        float v = 0.0f;
        for (int k = 0; k < NWARP; k++) v += wsum[k * P + tid];
        expv[tid] = v;
    }
    __syncthreads();

    // ---- decode + residual ----
    const float al = alpha[0];
    const int base = n * P * D;
    for (int e = tid; e < P * D; e += TPB) {
        const int w = e >> 6;
        const int d = e & 63;
        out[base + e] = h[base + e] + al * expv[w] * dec_w[d];
    }
}

} // anonymous namespace

extern "C" void kernel_launch(void* const* d_in, const int* in_sizes, int n_in,
                              void* d_out, int out_size)
{
    const float* h     = (const float*)d_in[0];
    const float* enc_w = (const float*)d_in[1];
    const float* enc_b = (const float*)d_in[2];
    const float* qw    = (const float*)d_in[3];
    const float* dec_w = (const float*)d_in[4];
    const float* alpha = (const float*)d_in[5];
    float* out = (float*)d_out;

    const int nsamp = in_sizes[0] / (P * D);   // B*T

    cudaFuncSetAttribute(qlc_kernel, cudaFuncAttributeMaxDynamicSharedMemorySize, SMEM_BYTES);
    qlc_kernel<<<nsamp, TPB, SMEM_BYTES>>>(h, enc_w, enc_b, qw, dec_w, alpha, out);
}